// round 8
// baseline (speedup 1.0000x reference)
#include <cuda_runtime.h>
#include <cuda_fp16.h>
#include <cstdint>

#define NDIM 128
#define MAX_NODES 100000

// Scratch: fp16 z table, fp16 x_source copy, even/odd-interleaved W, dtype flag.
__device__ __half g_z_h[MAX_NODES * NDIM];    // 25.6 MB
__device__ __half g_xs_h[MAX_NODES * NDIM];   // 25.6 MB
__device__ float  g_Wt2[NDIM * NDIM];         // Wt2[fp][d] = (W[d][2fp], W[d][2fp+1])
__device__ int    g_idx_is64;

// ---------------------------------------------------------------------------
// Kernel 0: detect index dtype (int64 values < 2^31 -> all odd words zero).
// ---------------------------------------------------------------------------
__global__ void detect_idx_kernel(const int* __restrict__ idx_words, int nwords) {
    __shared__ int s_any_nonzero;
    if (threadIdx.x == 0) s_any_nonzero = 0;
    __syncthreads();
    for (int i = 1 + 2 * threadIdx.x; i < nwords; i += 2 * blockDim.x) {
        if (idx_words[i] != 0) { s_any_nonzero = 1; break; }
    }
    __syncthreads();
    if (threadIdx.x == 0) g_idx_is64 = (s_any_nonzero == 0) ? 1 : 0;
}

// ---------------------------------------------------------------------------
// Kernel 1: build even/odd-interleaved W table.
// g_Wt2[(fp*128 + d)*2 + {0,1}] = W[d][2fp], W[d][2fp+1]
// ---------------------------------------------------------------------------
__global__ void build_Wt2_kernel(const float* __restrict__ W) {
    int fp = blockIdx.x;     // 0..63 (f-pair)
    int d  = threadIdx.x;    // 0..127 (coalesced 8B stores)
    float2 v = make_float2(W[d * NDIM + 2 * fp], W[d * NDIM + 2 * fp + 1]);
    *(float2*)(g_Wt2 + ((size_t)fp * NDIM + d) * 2) = v;
}

// ---------------------------------------------------------------------------
// Kernel 2: convert x_source -> fp16 (vectorized x4)
// ---------------------------------------------------------------------------
__global__ void __launch_bounds__(256) convert_xs_kernel(const float* __restrict__ xs,
                                                         int n_elem4) {
    int i = blockIdx.x * blockDim.x + threadIdx.x;
    if (i >= n_elem4) return;
    float4 v = *(const float4*)(xs + (size_t)i * 4);
    *(__half2*)(g_xs_h + (size_t)i * 4)     = __floats2half2_rn(v.x, v.y);
    *(__half2*)(g_xs_h + (size_t)i * 4 + 2) = __floats2half2_rn(v.z, v.w);
}

// ---------------------------------------------------------------------------
// Kernel 3: z = x_target @ W^T  using packed fma.rn.f32x2 (FFMA2).
// Same tiling as the proven R3 kernel: 256 thr / 8 warps, 32 rows per block,
// 4 rows per warp, 4 output cols per lane. Reduction split even/odd f across
// the two packed fp32 lanes; combined at the end (lo + hi).
// ---------------------------------------------------------------------------
__device__ __forceinline__ void ffma2(unsigned long long& acc,
                                      unsigned long long a,
                                      unsigned long long b) {
    asm("fma.rn.f32x2 %0, %1, %2, %0;" : "+l"(acc) : "l"(a), "l"(b));
}

__device__ __forceinline__ float unpack_sum(unsigned long long p) {
    unsigned int lo, hi;
    asm("mov.b64 {%0, %1}, %2;" : "=r"(lo), "=r"(hi) : "l"(p));
    return __uint_as_float(lo) + __uint_as_float(hi);
}

__global__ void __launch_bounds__(256) gemm_zt2_kernel(const float* __restrict__ xt,
                                                       int n_rows) {
    __shared__ float s_x[32][NDIM];   // 16 KB tile

    const int warp = threadIdx.x >> 5;
    const int lane = threadIdx.x & 31;
    const int base = blockIdx.x * 32;

    for (int i = threadIdx.x; i < 32 * NDIM; i += blockDim.x) {
        int r = i >> 7;
        int c = i & (NDIM - 1);
        int row = base + r;
        s_x[r][c] = (row < n_rows) ? xt[(size_t)row * NDIM + c] : 0.0f;
    }
    __syncthreads();

    const int r0  = warp * 4;
    const int col = lane * 4;

    unsigned long long acc[4][4];   // [row][col] packed (even-f, odd-f) partials
#pragma unroll
    for (int r = 0; r < 4; r++)
#pragma unroll
        for (int c = 0; c < 4; c++) acc[r][c] = 0ull;   // (+0.f, +0.f)

    const float* wbase = g_Wt2 + (size_t)col * 2;

#pragma unroll 2
    for (int fp = 0; fp < NDIM / 2; fp++) {
        // W pairs for 4 cols: 32 contiguous bytes -> two 16B loads
        ulonglong2 w01 = *(const ulonglong2*)(wbase + (size_t)fp * (NDIM * 2));
        ulonglong2 w23 = *(const ulonglong2*)(wbase + (size_t)fp * (NDIM * 2) + 4);

        // x pairs for 4 rows (LDS.64, warp-broadcast)
        unsigned long long x0 = *(const unsigned long long*)&s_x[r0 + 0][fp * 2];
        unsigned long long x1 = *(const unsigned long long*)&s_x[r0 + 1][fp * 2];
        unsigned long long x2 = *(const unsigned long long*)&s_x[r0 + 2][fp * 2];
        unsigned long long x3 = *(const unsigned long long*)&s_x[r0 + 3][fp * 2];

        ffma2(acc[0][0], x0, w01.x); ffma2(acc[0][1], x0, w01.y);
        ffma2(acc[0][2], x0, w23.x); ffma2(acc[0][3], x0, w23.y);
        ffma2(acc[1][0], x1, w01.x); ffma2(acc[1][1], x1, w01.y);
        ffma2(acc[1][2], x1, w23.x); ffma2(acc[1][3], x1, w23.y);
        ffma2(acc[2][0], x2, w01.x); ffma2(acc[2][1], x2, w01.y);
        ffma2(acc[2][2], x2, w23.x); ffma2(acc[2][3], x2, w23.y);
        ffma2(acc[3][0], x3, w01.x); ffma2(acc[3][1], x3, w01.y);
        ffma2(acc[3][2], x3, w23.x); ffma2(acc[3][3], x3, w23.y);
    }

#pragma unroll
    for (int r = 0; r < 4; r++) {
        int row = base + r0 + r;
        if (row < n_rows) {
            float v0 = unpack_sum(acc[r][0]);
            float v1 = unpack_sum(acc[r][1]);
            float v2 = unpack_sum(acc[r][2]);
            float v3 = unpack_sum(acc[r][3]);
            __half2* p = (__half2*)(g_z_h + (size_t)row * NDIM + col);
            p[0] = __floats2half2_rn(v0, v1);
            p[1] = __floats2half2_rn(v2, v3);
        }
    }
}

// ---------------------------------------------------------------------------
// Kernel 4: per-edge dot on fp16 tables (unchanged from the 225.6us pass).
// 16 lanes per edge, 8 edges per warp (4 unrolled pairs), all loads hoisted.
// ---------------------------------------------------------------------------
__device__ __forceinline__ float dot8h(float4 a, float4 v) {
    const __half2* ah = (const __half2*)&a;
    const __half2* vh = (const __half2*)&v;
    float acc = 0.f;
#pragma unroll
    for (int i = 0; i < 4; i++) {
        float2 af = __half22float2(ah[i]);
        float2 vf = __half22float2(vh[i]);
        acc += af.x * vf.x + af.y * vf.y;
    }
    return acc;
}

#define EDGES_PER_WARP 8

__global__ void __launch_bounds__(256) edge_dot_kernel(
    const void* __restrict__ eli_raw,
    const float* __restrict__ bias,
    float* __restrict__ out,
    int E, int N) {
    const int gwarp = (blockIdx.x * blockDim.x + threadIdx.x) >> 5;
    const int lane  = threadIdx.x & 31;
    const int half  = lane >> 4;
    const int sub   = lane & 15;

    const int e0 = gwarp * EDGES_PER_WARP;
    if (e0 >= E) return;

    const int is64 = g_idx_is64;
    const long long* eli64 = (const long long*)eli_raw;
    const int*       eli32 = (const int*)eli_raw;

    int eidx[4];
    long long sIdx[4], tIdx[4];
#pragma unroll
    for (int j = 0; j < 4; j++) {
        int e = e0 + 2 * j + half;
        if (e >= E) e = E - 1;
        eidx[j] = e;
        long long s, t;
        if (is64) { s = __ldg(&eli64[e]); t = __ldg(&eli64[(long long)E + e]); }
        else      { s = __ldg(&eli32[e]); t = __ldg(&eli32[(long long)E + e]); }
        if (s < 0) s = 0; if (s >= N) s = N - 1;
        if (t < 0) t = 0; if (t >= N) t = N - 1;
        sIdx[j] = s; tIdx[j] = t;
    }

    float4 a[4], v[4];
#pragma unroll
    for (int j = 0; j < 4; j++) {
        a[j] = __ldg((const float4*)(g_xs_h + ((size_t)sIdx[j] << 7) + (sub << 3)));
        v[j] = __ldg((const float4*)(g_z_h  + ((size_t)tIdx[j] << 7) + (sub << 3)));
    }

    const float bv = __ldg(bias);

#pragma unroll
    for (int j = 0; j < 4; j++) {
        float acc = dot8h(a[j], v[j]);
#pragma unroll
        for (int o = 8; o > 0; o >>= 1)
            acc += __shfl_down_sync(0xFFFFFFFFu, acc, o, 16);
        if (sub == 0 && (e0 + 2 * j + half) < E)
            out[eidx[j]] = acc + bv;
    }
}

// ---------------------------------------------------------------------------
extern "C" void kernel_launch(void* const* d_in, const int* in_sizes, int n_in,
                              void* d_out, int out_size) {
    const float* x_source = nullptr;
    const float* x_target = nullptr;
    const void*  eli      = nullptr;
    const float* W        = nullptr;
    const float* bias     = nullptr;
    int N = 0;
    const int E = out_size;

    for (int i = 0; i < n_in; i++) {
        int sz = in_sizes[i];
        if (sz == NDIM * NDIM)      W    = (const float*)d_in[i];
        else if (sz == 1)           bias = (const float*)d_in[i];
        else if (sz == 2 * E)       eli  = d_in[i];
        else {
            if (!x_source) { x_source = (const float*)d_in[i]; N = sz / NDIM; }
            else           { x_target = (const float*)d_in[i]; }
        }
    }

    float* out = (float*)d_out;

    // 0) detect index dtype
    int nwords = 2 * E; if (nwords > 4096) nwords = 4096;
    detect_idx_kernel<<<1, 256>>>((const int*)eli, nwords);

    // 1) build interleaved W; convert x_source -> fp16
    build_Wt2_kernel<<<NDIM / 2, NDIM>>>(W);
    int n_elem4 = (N * NDIM) / 4;
    convert_xs_kernel<<<(n_elem4 + 255) / 256, 256>>>(x_source, n_elem4);

    // 2) z = x_target @ W^T  (packed FFMA2)
    gemm_zt2_kernel<<<(N + 31) / 32, 256>>>(x_target, N);

    // 3) per-edge gather + dot
    int warps_needed = (E + EDGES_PER_WARP - 1) / EDGES_PER_WARP;
    int nblocks = (warps_needed + 7) / 8;
    edge_dot_kernel<<<nblocks, 256>>>(eli, bias, out, E, N);
}